// round 11
// baseline (speedup 1.0000x reference)
#include <cuda_runtime.h>
#include <cuda_bf16.h>
#include <math.h>
#include <stdint.h>

// Problem constants
#define BB    16
#define NP1   65
#define TOK   (BB*NP1)      // 1040
#define MM    256
#define DD    512
#define HH    8
#define DH    64
#define LL    3
#define DFF   2048

// ---------------- weight arena offsets (elements) ---------------------------
#define W_QKV 0
#define W_OUT 2359296
#define W_FF1 3145728
#define W_FF2 6291456
#define W_U   9437184
#define W_H   9568256
#define W_TOT 9699328

// ---------------- scratch (device globals; no allocation allowed) ----------
__device__ __align__(128) float          g_xs  [TOK*DD];
__device__ __align__(128) __nv_bfloat16  g_xsh [TOK*DD];
__device__ __align__(128) __nv_bfloat16  g_xsl [TOK*DD];
__device__ __align__(128) float          g_qkv [TOK*3*DD];
__device__ __align__(128) __nv_bfloat16  g_ath [TOK*DD];
__device__ __align__(128) __nv_bfloat16  g_atl [TOK*DD];
__device__ __align__(128) float          g_tmp [TOK*DD];
__device__ __align__(128) __nv_bfloat16  g_ffh [TOK*DFF];
__device__ __align__(128) __nv_bfloat16  g_ffl [TOK*DFF];
__device__ __align__(128) float          g_hraw[TOK*MM];
__device__ __align__(128) __nv_bfloat16  g_wh  [W_TOT];
__device__ __align__(128) __nv_bfloat16  g_wl  [W_TOT];

// ---------------- PTX helpers (portable to bare sm_103) ---------------------
__device__ __forceinline__ uint32_t s2u(const void* p) {
    uint32_t a;
    asm("{ .reg .u64 t; cvta.to.shared.u64 t, %1; cvt.u32.u64 %0, t; }" : "=r"(a) : "l"(p));
    return a;
}
__device__ __forceinline__ void cp16(uint32_t dst, const void* src) {
    unsigned long long g = (unsigned long long)__cvta_generic_to_global(src);
    asm volatile("cp.async.cg.shared.global [%0], [%1], 16;" :: "r"(dst), "l"(g) : "memory");
}
#define CP_COMMIT() asm volatile("cp.async.commit_group;" ::: "memory")
#define CP_WAIT(n)  asm volatile("cp.async.wait_group %0;" :: "n"(n) : "memory")

__device__ __forceinline__ void ldm4(uint32_t* r, uint32_t a) {
    asm volatile("ldmatrix.sync.aligned.m8n8.x4.shared.b16 {%0,%1,%2,%3}, [%4];"
        : "=r"(r[0]), "=r"(r[1]), "=r"(r[2]), "=r"(r[3]) : "r"(a));
}
__device__ __forceinline__ void mma16816(float* c, const uint32_t* a, uint32_t b0, uint32_t b1) {
    asm volatile("mma.sync.aligned.m16n8k16.row.col.f32.bf16.bf16.f32 "
        "{%0,%1,%2,%3}, {%4,%5,%6,%7}, {%8,%9}, {%0,%1,%2,%3};"
        : "+f"(c[0]), "+f"(c[1]), "+f"(c[2]), "+f"(c[3])
        : "r"(a[0]), "r"(a[1]), "r"(a[2]), "r"(a[3]), "r"(b0), "r"(b1));
}

// ---------------- fused weight split: fp32 arena -> bf16 hi/lo --------------
__global__ __launch_bounds__(256)
void split_all(const float* __restrict__ qkvw, const float* __restrict__ outw,
               const float* __restrict__ ff1w, const float* __restrict__ ff2w,
               const float* __restrict__ uw,   const float* __restrict__ hw,
               __nv_bfloat16* __restrict__ wh, __nv_bfloat16* __restrict__ wl)
{
    size_t i = ((size_t)blockIdx.x*256 + threadIdx.x)*4;
    if (i >= W_TOT) return;
    const float* src;
    if      (i < W_OUT) src = qkvw + i;
    else if (i < W_FF1) src = outw + (i - W_OUT);
    else if (i < W_FF2) src = ff1w + (i - W_FF1);
    else if (i < W_U)   src = ff2w + (i - W_FF2);
    else if (i < W_H)   src = uw   + (i - W_U);
    else                src = hw   + (i - W_H);
    float4 v = *(const float4*)src;
    __nv_bfloat16 h0 = __float2bfloat16_rn(v.x), h1 = __float2bfloat16_rn(v.y);
    __nv_bfloat16 h2 = __float2bfloat16_rn(v.z), h3 = __float2bfloat16_rn(v.w);
    __nv_bfloat162 hp0; hp0.x = h0; hp0.y = h1;
    __nv_bfloat162 hp1; hp1.x = h2; hp1.y = h3;
    ((__nv_bfloat162*)(wh + i))[0] = hp0;
    ((__nv_bfloat162*)(wh + i))[1] = hp1;
    __nv_bfloat162 lp0, lp1;
    lp0.x = __float2bfloat16_rn(v.x - __bfloat162float(h0));
    lp0.y = __float2bfloat16_rn(v.y - __bfloat162float(h1));
    lp1.x = __float2bfloat16_rn(v.z - __bfloat162float(h2));
    lp1.y = __float2bfloat16_rn(v.w - __bfloat162float(h3));
    ((__nv_bfloat162*)(wl + i))[0] = lp0;
    ((__nv_bfloat162*)(wl + i))[1] = lp1;
}

// ---------------- HMMA GEMM: C[m,n] = sum_k A[m,k]*W[n,k] + bias ------------
// Tile BM x BN, NTHR threads. Warps: WM(M) x BN/32(N); warp tile (BM/WM)x32.
// NST-stage cp.async pipeline, K-chunk 32. 3-term split: Ah*Wh + Ah*Wl + Al*Wh.
#define LDS_B 80     // padded row stride (64B payload + 16B pad)

template<int BM, int BN, int NTHR>
__device__ __forceinline__ void load_chunk(uint32_t sb, int stage,
    const __nv_bfloat16* Ah, const __nv_bfloat16* Al,
    const __nv_bfloat16* Wh, const __nv_bfloat16* Wl,
    int m0, int n0, int k0, int M, int K, int tid)
{
    constexpr int AS_LO = BM*LDS_B;
    constexpr int WS_HI = 2*BM*LDS_B;
    constexpr int WS_LO = (2*BM+BN)*LDS_B;
    constexpr int STG   = (2*BM+2*BN)*LDS_B;
    constexpr int AIT   = (BM*4)/NTHR;
    constexpr int WIT   = (BN*4)/NTHR;
    uint32_t st = sb + stage*STG;
    #pragma unroll
    for (int p = 0; p < AIT; p++) {
        int idx = tid + p*NTHR;
        int row = idx >> 2, g = idx & 3;
        int ar = m0 + row; if (ar >= M) ar = M - 1;
        size_t off = (size_t)ar*K + k0 + g*8;
        uint32_t d = row*LDS_B + g*16;
        cp16(st + d,         Ah + off);
        cp16(st + AS_LO + d, Al + off);
    }
    #pragma unroll
    for (int p = 0; p < WIT; p++) {
        int idx = tid + p*NTHR;
        int row = idx >> 2, g = idx & 3;
        size_t off = (size_t)(n0 + row)*K + k0 + g*8;
        uint32_t d = row*LDS_B + g*16;
        cp16(st + WS_HI + d, Wh + off);
        cp16(st + WS_LO + d, Wl + off);
    }
}

template<int EPI, int BM, int BN, int NTHR, int NST>
__global__ __launch_bounds__(NTHR, 2)
void mma_gemm(const __nv_bfloat16* __restrict__ Ah, const __nv_bfloat16* __restrict__ Al,
              const __nv_bfloat16* __restrict__ Wh, const __nv_bfloat16* __restrict__ Wl,
              const float* __restrict__ b0, const float* __restrict__ b1,
              float* __restrict__ C0, float* __restrict__ C1,
              __nv_bfloat16* __restrict__ Ch, __nv_bfloat16* __restrict__ Cl,
              int M, int N, int K)
{
    extern __shared__ char smem[];
    constexpr int NWARP = NTHR/32;
    constexpr int WN    = BN/32;
    constexpr int WMCNT = NWARP/WN;
    constexpr int WROWS = BM/WMCNT;
    constexpr int IT    = WROWS/16;
    constexpr int AS_LO = BM*LDS_B;
    constexpr int WS_HI = 2*BM*LDS_B;
    constexpr int STG   = (2*BM+2*BN)*LDS_B;
    uint32_t sb = s2u(smem);
    int tid = threadIdx.x, wid = tid >> 5, lane = tid & 31;
    int wm = wid / WN, wn = wid % WN;
    int m0 = blockIdx.y * BM, n0 = blockIdx.x * BN;
    const int NC = K >> 5;

    float c[IT][4][4];
    #pragma unroll
    for (int i = 0; i < IT; i++)
        #pragma unroll
        for (int j = 0; j < 4; j++)
            #pragma unroll
            for (int q = 0; q < 4; q++) c[i][j][q] = 0.f;

    #pragma unroll
    for (int s = 0; s < NST; s++) {
        load_chunk<BM,BN,NTHR>(sb, s, Ah, Al, Wh, Wl, m0, n0, s*32, M, K, tid);
        CP_COMMIT();
    }

    uint32_t lrow = (lane & 15);
    uint32_t koff = (lane >> 4) * 16;

    for (int cc = 0; cc < NC; cc++) {
        CP_WAIT(NST - 1);
        __syncthreads();
        uint32_t st = sb + (cc % NST)*STG;
        #pragma unroll
        for (int ks = 0; ks < 2; ks++) {
            uint32_t kb = ks*32 + koff;
            uint32_t bh[2][4], bl[2][4];
            #pragma unroll
            for (int j2 = 0; j2 < 2; j2++) {
                uint32_t rb = st + WS_HI + (wn*32 + j2*16 + lrow)*LDS_B + kb;
                ldm4(bh[j2], rb);
                ldm4(bl[j2], rb + BN*LDS_B);
            }
            #pragma unroll
            for (int i = 0; i < IT; i++) {
                uint32_t ra = st + (wm*WROWS + i*16 + lrow)*LDS_B + kb;
                uint32_t ah[4], al[4];
                ldm4(ah, ra);
                ldm4(al, ra + AS_LO);
                #pragma unroll
                for (int j2 = 0; j2 < 2; j2++) {
                    #pragma unroll
                    for (int jj = 0; jj < 2; jj++) {
                        float* acc = c[i][2*j2 + jj];
                        mma16816(acc, ah, bh[j2][jj], bh[j2][jj+2]);
                        mma16816(acc, ah, bl[j2][jj], bl[j2][jj+2]);
                        mma16816(acc, al, bh[j2][jj], bh[j2][jj+2]);
                    }
                }
            }
        }
        __syncthreads();
        if (cc + NST < NC)
            load_chunk<BM,BN,NTHR>(sb, cc % NST, Ah, Al, Wh, Wl, m0, n0, (cc+NST)*32, M, K, tid);
        CP_COMMIT();
    }

    // epilogue
    int rbase = m0 + wm*WROWS + (lane >> 2);
    int cbase = n0 + wn*32 + 2*(lane & 3);
    #pragma unroll
    for (int i = 0; i < IT; i++) {
        #pragma unroll
        for (int j = 0; j < 4; j++) {
            int col = cbase + j*8;
            float bb0 = b0[col], bb1 = b0[col+1];
            #pragma unroll
            for (int half = 0; half < 2; half++) {
                int r = rbase + i*16 + half*8;
                if (r >= M) continue;
                float v0 = c[i][j][2*half + 0] + bb0;
                float v1 = c[i][j][2*half + 1] + bb1;
                if (EPI == 0) {
                    *(float2*)(C0 + (size_t)r*N + col) = make_float2(v0, v1);
                } else if (EPI == 1) {
                    v0 = 0.5f*v0*(1.0f + erff(v0*0.70710678118654752f));
                    v1 = 0.5f*v1*(1.0f + erff(v1*0.70710678118654752f));
                    __nv_bfloat16 h0 = __float2bfloat16_rn(v0);
                    __nv_bfloat16 h1 = __float2bfloat16_rn(v1);
                    __nv_bfloat162 hp; hp.x = h0; hp.y = h1;
                    __nv_bfloat162 lp;
                    lp.x = __float2bfloat16_rn(v0 - __bfloat162float(h0));
                    lp.y = __float2bfloat16_rn(v1 - __bfloat162float(h1));
                    *(__nv_bfloat162*)(Ch + (size_t)r*N + col) = hp;
                    *(__nv_bfloat162*)(Cl + (size_t)r*N + col) = lp;
                } else {
                    if (col < 256) {
                        *(float2*)(C0 + (size_t)r*256 + col) = make_float2(v0, v1);
                    } else {
                        float u0 = c[i][j][2*half+0] + b1[col-256];
                        float u1 = c[i][j][2*half+1] + b1[col-255];
                        *(float2*)(C1 + (size_t)r*256 + (col-256)) = make_float2(u0, u1);
                    }
                }
            }
        }
    }
}

// ---------------- embed: conv-collapse + fc + LN + GELU + pos --------------
__global__ __launch_bounds__(256)
void embed_kernel(const float* __restrict__ marg, const float* __restrict__ conv_w,
                  const float* __restrict__ conv_b, const float* __restrict__ fc_w,
                  const float* __restrict__ fc_b, const float* __restrict__ ln_g,
                  const float* __restrict__ ln_b, const float* __restrict__ pos,
                  float* __restrict__ xs, __nv_bfloat16* __restrict__ xsh,
                  __nv_bfloat16* __restrict__ xsl)
{
    int row = blockIdx.x;
    int tid = threadIdx.x;
    __shared__ float red[256];
    __shared__ float e[128];

    const float* x = marg + (size_t)row * MM;
    red[tid] = x[tid];
    __syncthreads();
    for (int s = 128; s > 0; s >>= 1) { if (tid < s) red[tid] += red[tid+s]; __syncthreads(); }
    float S = red[0];
    __syncthreads();

    if (tid < 128) {
        float x0 = x[0], x1 = x[1], xm2 = x[MM-2], xm1 = x[MM-1];
        const float* w = conv_w + tid*5;
        float acc = w[0]*(S - xm2 - xm1) + w[1]*(S - xm1) + w[2]*S
                  + w[3]*(S - x0)        + w[4]*(S - x0 - x1);
        e[tid] = conv_b[tid] + acc * (1.0f/(float)MM);
    }
    __syncthreads();

    float t0 = fc_b[tid], t1 = fc_b[tid+256];
    #pragma unroll 4
    for (int c = 0; c < 128; c++) {
        float ec = e[c];
        t0 += ec * fc_w[c*DD + tid];
        t1 += ec * fc_w[c*DD + tid + 256];
    }

    red[tid] = t0 + t1; __syncthreads();
    for (int s = 128; s > 0; s >>= 1) { if (tid < s) red[tid] += red[tid+s]; __syncthreads(); }
    float mean = red[0] * (1.0f/(float)DD);
    __syncthreads();
    float d0 = t0 - mean, d1 = t1 - mean;
    red[tid] = d0*d0 + d1*d1; __syncthreads();
    for (int s = 128; s > 0; s >>= 1) { if (tid < s) red[tid] += red[tid+s]; __syncthreads(); }
    float inv = rsqrtf(red[0] * (1.0f/(float)DD) + 1e-5f);

    float y0 = d0*inv*ln_g[tid]     + ln_b[tid];
    float y1 = d1*inv*ln_g[tid+256] + ln_b[tid+256];
    y0 = 0.5f*y0*(1.0f + erff(y0*0.70710678118654752f));
    y1 = 0.5f*y1*(1.0f + erff(y1*0.70710678118654752f));

    int p = row % NP1;
    float v0 = y0 + pos[p*DD + tid];
    float v1 = y1 + pos[p*DD + tid + 256];
    size_t base = (size_t)row*DD;
    xs[base + tid] = v0; xs[base + tid + 256] = v1;
    __nv_bfloat16 h0 = __float2bfloat16_rn(v0), h1 = __float2bfloat16_rn(v1);
    xsh[base + tid] = h0;        xsh[base + tid + 256] = h1;
    xsl[base + tid] = __float2bfloat16_rn(v0 - __bfloat162float(h0));
    xsl[base + tid + 256] = __float2bfloat16_rn(v1 - __bfloat162float(h1));
}

// ---------------- attention: one block per (b,h), 16 warps, 4 queries/warp -
// Single pass: warp w handles queries 4w..4w+3 as 4 ILP streams sharing K/V
// smem loads. Query 64 handled by warp 0 in a short single-stream tail.
#define ATTN_SMEM ((NP1*65 + NP1*64 + 64*68)*4)   // Ks + Vs + Ps

__global__ __launch_bounds__(512)
void attn_kernel(const float* __restrict__ qkv, __nv_bfloat16* __restrict__ ah,
                 __nv_bfloat16* __restrict__ al)
{
    extern __shared__ float asm_f[];
    float (*Ks)[65] = (float(*)[65])asm_f;                       // [NP1][65]
    float (*Vs)[64] = (float(*)[64])(asm_f + NP1*65);            // [NP1][64]
    float (*Ps)[68] = (float(*)[68])(asm_f + NP1*65 + NP1*64);   // [64][68]

    int bh = blockIdx.x;
    int b = bh >> 3, h = bh & 7;
    int tid = threadIdx.x, lane = tid & 31, w = tid >> 5;   // w: 0..15

    for (int idx = tid; idx < NP1*64; idx += 512) {
        int j = idx >> 6, k = idx & 63;
        size_t base = ((size_t)(b*NP1 + j))*(3*DD) + h*DH + k;
        Ks[j][k] = qkv[base + DD];
        Vs[j][k] = qkv[base + 2*DD];
    }
    __syncthreads();

    const float scale = 0.125f;
    const unsigned FULL = 0xffffffffu;
    int q0 = w*4;

    float2 qp[4];
    #pragma unroll
    for (int s = 0; s < 4; s++)
        qp[s] = *(const float2*)(qkv + ((size_t)(b*NP1 + q0 + s))*(3*DD) + h*DH + 2*lane);

    float sc[4][3];
    #pragma unroll
    for (int s = 0; s < 4; s++) { sc[s][0] = 0.f; sc[s][1] = 0.f; sc[s][2] = 0.f; }

    #pragma unroll
    for (int k = 0; k < 64; k++) {
        float k0 = Ks[lane][k], k1 = Ks[lane + 32][k], k2 = Ks[64][k];
        #pragma unroll
        for (int s = 0; s < 4; s++) {
            float qv = __shfl_sync(FULL, (k & 1) ? qp[s].y : qp[s].x, k >> 1);
            sc[s][0] = fmaf(qv, k0, sc[s][0]);
            sc[s][1] = fmaf(qv, k1, sc[s][1]);
            sc[s][2] = fmaf(qv, k2, sc[s][2]);
        }
    }

    float mx[4], e0[4], e1[4], e2[4], ls[4], rinv[4];
    #pragma unroll
    for (int s = 0; s < 4; s++) {
        sc[s][0] *= scale; sc[s][1] *= scale; sc[s][2] *= scale;
        mx[s] = fmaxf(fmaxf(sc[s][0], sc[s][1]), sc[s][2]);
    }
    #pragma unroll
    for (int o = 16; o > 0; o >>= 1)
        #pragma unroll
        for (int s = 0; s < 4; s++)
            mx[s] = fmaxf(mx[s], __shfl_xor_sync(FULL, mx[s], o));
    #pragma unroll
    for (int s = 0; s < 4; s++) {
        e0[s] = expf(sc[s][0] - mx[s]);
        e1[s] = expf(sc[s][1] - mx[s]);
        e2[s] = expf(sc[s][2] - mx[s]);
        ls[s] = e0[s] + e1[s];
    }
    #pragma unroll
    for (int o = 16; o > 0; o >>= 1)
        #pragma unroll
        for (int s = 0; s < 4; s++)
            ls[s] += __shfl_xor_sync(FULL, ls[s], o);
    #pragma unroll
    for (int s = 0; s < 4; s++) {
        rinv[s] = 1.0f / (ls[s] + e2[s]);
        Ps[q0 + s][lane]      = e0[s] * rinv[s];
        Ps[q0 + s][lane + 32] = e1[s] * rinv[s];
        if (lane == 0) Ps[q0 + s][64] = e2[s] * rinv[s];
    }
    __syncwarp();

    float o0[4], o1[4];
    #pragma unroll
    for (int s = 0; s < 4; s++) { o0[s] = 0.f; o1[s] = 0.f; }
    #pragma unroll 5
    for (int j = 0; j < NP1; j++) {
        float v0 = Vs[j][lane], v1 = Vs[j][lane + 32];
        #pragma unroll
        for (int s = 0; s < 4; s++) {
            float pj = Ps[q0 + s][j];
            o0[s] = fmaf(pj, v0, o0[s]);
            o1[s] = fmaf(pj, v1, o1[s]);
        }
    }
    #pragma unroll
    for (int s = 0; s < 4; s++) {
        size_t obase = ((size_t)(b*NP1 + q0 + s))*DD + h*DH;
        __nv_bfloat16 h0 = __float2bfloat16_rn(o0[s]), h1 = __float2bfloat16_rn(o1[s]);
        ah[obase + lane]      = h0;
        ah[obase + lane + 32] = h1;
        al[obase + lane]      = __float2bfloat16_rn(o0[s] - __bfloat162float(h0));
        al[obase + lane + 32] = __float2bfloat16_rn(o1[s] - __bfloat162float(h1));
    }

    // tail: query 64 on warp 0 only (other warps done)
    if (w == 0) {
        __syncwarp();
        float2 qt = *(const float2*)(qkv + ((size_t)(b*NP1 + 64))*(3*DD) + h*DH + 2*lane);
        float t0 = 0.f, t1 = 0.f, t2 = 0.f;
        #pragma unroll
        for (int k = 0; k < 64; k++) {
            float qv = __shfl_sync(FULL, (k & 1) ? qt.y : qt.x, k >> 1);
            t0 = fmaf(qv, Ks[lane][k],      t0);
            t1 = fmaf(qv, Ks[lane + 32][k], t1);
            t2 = fmaf(qv, Ks[64][k],        t2);
        }
        t0 *= scale; t1 *= scale; t2 *= scale;
        float m = fmaxf(fmaxf(t0, t1), t2);
        #pragma unroll
        for (int o = 16; o > 0; o >>= 1) m = fmaxf(m, __shfl_xor_sync(FULL, m, o));
        float f0 = expf(t0 - m), f1 = expf(t1 - m), f2 = expf(t2 - m);
        float l = f0 + f1;
        #pragma unroll
        for (int o = 16; o > 0; o >>= 1) l += __shfl_xor_sync(FULL, l, o);
        float ri = 1.0f / (l + f2);
        Ps[0][lane]      = f0 * ri;
        Ps[0][lane + 32] = f1 * ri;
        if (lane == 0) Ps[0][64] = f2 * ri;
        __syncwarp();
        float u0 = 0.f, u1 = 0.f;
        #pragma unroll 5
        for (int j = 0; j < NP1; j++) {
            float pj = Ps[0][j];
            u0 = fmaf(pj, Vs[j][lane],      u0);
            u1 = fmaf(pj, Vs[j][lane + 32], u1);
        }
        size_t obase = ((size_t)(b*NP1 + 64))*DD + h*DH;
        __nv_bfloat16 h0 = __float2bfloat16_rn(u0), h1 = __float2bfloat16_rn(u1);
        ah[obase + lane]      = h0;
        ah[obase + lane + 32] = h1;
        al[obase + lane]      = __float2bfloat16_rn(u0 - __bfloat162float(h0));
        al[obase + lane + 32] = __float2bfloat16_rn(u1 - __bfloat162float(h1));
    }
}

// ---------------- residual + LayerNorm (in place on xs), emits hi/lo -------
__global__ __launch_bounds__(256)
void ln_res_kernel(const float* __restrict__ add, const float* __restrict__ g,
                   const float* __restrict__ bta, float* __restrict__ xs,
                   __nv_bfloat16* __restrict__ xsh, __nv_bfloat16* __restrict__ xsl)
{
    int row = blockIdx.x, tid = threadIdx.x;
    __shared__ float red[256];
    size_t base = (size_t)row*DD;
    float v0 = xs[base + tid]       + add[base + tid];
    float v1 = xs[base + tid + 256] + add[base + tid + 256];

    red[tid] = v0 + v1; __syncthreads();
    for (int s = 128; s > 0; s >>= 1) { if (tid < s) red[tid] += red[tid+s]; __syncthreads(); }
    float mean = red[0] * (1.0f/(float)DD);
    __syncthreads();
    float d0 = v0 - mean, d1 = v1 - mean;
    red[tid] = d0*d0 + d1*d1; __syncthreads();
    for (int s = 128; s > 0; s >>= 1) { if (tid < s) red[tid] += red[tid+s]; __syncthreads(); }
    float inv = rsqrtf(red[0] * (1.0f/(float)DD) + 1e-5f);

    float y0 = d0*inv*g[tid]       + bta[tid];
    float y1 = d1*inv*g[tid + 256] + bta[tid + 256];
    xs[base + tid] = y0; xs[base + tid + 256] = y1;
    __nv_bfloat16 h0 = __float2bfloat16_rn(y0), h1 = __float2bfloat16_rn(y1);
    xsh[base + tid] = h0;        xsh[base + tid + 256] = h1;
    xsl[base + tid] = __float2bfloat16_rn(y0 - __bfloat162float(h0));
    xsl[base + tid + 256] = __float2bfloat16_rn(y1 - __bfloat162float(h1));
}

// ---------------- MMOT tail: closed-form truncated-geometric softmax -------
__global__ __launch_bounds__(256)
void tail_kernel(const float* __restrict__ hraw, const float* __restrict__ marg,
                 const float* __restrict__ xg, float* __restrict__ hout)
{
    int blk = blockIdx.x;
    int b = blk >> 6, n = blk & 63;
    int tid = threadIdx.x;
    int tok = b*NP1 + n;

    float hr = hraw[(size_t)tok*MM + tid];
    const float DELTA = 6.0f/255.0f;
    float t = hr * (DELTA / 0.01f);
    float q = expf(-fabsf(t));

    float S0 = 1.f, S1 = 0.f, p = q, mcnt = 1.f;
    #pragma unroll
    for (int it = 0; it < 8; it++) {
        S1 = S1 + p*(S1 + mcnt*S0);
        S0 = S0 + p*S0;
        p  = p*p;
        mcnt *= 2.f;
    }
    float f = S1 / S0;
    if (t < 0.f) f = 255.f - f;

    float expected = -3.f + DELTA * f;
    float drift = expected - xg[tid];
    float mu = marg[(size_t)tok*MM + tid];

    __shared__ float r1[256], r2[256];
    r1[tid] = mu * drift; r2[tid] = mu;
    __syncthreads();
    for (int s = 128; s > 0; s >>= 1) {
        if (tid < s) { r1[tid] += r1[tid+s]; r2[tid] += r2[tid+s]; }
        __syncthreads();
    }
    float corr = r1[0] / (r2[0] + 1e-8f);
    hout[(size_t)(b*64 + n)*MM + tid] = hr - corr;
}

// ---------------------------------------------------------------------------
extern "C" void kernel_launch(void* const* d_in, const int* in_sizes, int n_in,
                              void* d_out, int out_size)
{
    const float* marg  = (const float*)d_in[0];
    const float* xg    = (const float*)d_in[1];
    const float* convw = (const float*)d_in[2];
    const float* convb = (const float*)d_in[3];
    const float* fcw   = (const float*)d_in[4];
    const float* fcb   = (const float*)d_in[5];
    const float* ln0g  = (const float*)d_in[6];
    const float* ln0b  = (const float*)d_in[7];
    const float* pos   = (const float*)d_in[8];
    const float* qkvw  = (const float*)d_in[9];
    const float* qkvb  = (const float*)d_in[10];
    const float* outw  = (const float*)d_in[11];
    const float* outb  = (const float*)d_in[12];
    const float* ln1g  = (const float*)d_in[13];
    const float* ln1b  = (const float*)d_in[14];
    const float* ff1w  = (const float*)d_in[15];
    const float* ff1b  = (const float*)d_in[16];
    const float* ff2w  = (const float*)d_in[17];
    const float* ff2b  = (const float*)d_in[18];
    const float* ln2g  = (const float*)d_in[19];
    const float* ln2b  = (const float*)d_in[20];
    const float* uw    = (const float*)d_in[21];
    const float* ub    = (const float*)d_in[22];
    const float* hw    = (const float*)d_in[23];
    const float* hb    = (const float*)d_in[24];

    float *xs, *qkv, *tmp, *hraw;
    __nv_bfloat16 *xsh, *xsl, *ath, *atl, *ffh, *ffl, *wh, *wl;
    cudaGetSymbolAddress((void**)&xs,   g_xs);
    cudaGetSymbolAddress((void**)&xsh,  g_xsh);
    cudaGetSymbolAddress((void**)&xsl,  g_xsl);
    cudaGetSymbolAddress((void**)&qkv,  g_qkv);
    cudaGetSymbolAddress((void**)&ath,  g_ath);
    cudaGetSymbolAddress((void**)&atl,  g_atl);
    cudaGetSymbolAddress((void**)&tmp,  g_tmp);
    cudaGetSymbolAddress((void**)&ffh,  g_ffh);
    cudaGetSymbolAddress((void**)&ffl,  g_ffl);
    cudaGetSymbolAddress((void**)&hraw, g_hraw);
    cudaGetSymbolAddress((void**)&wh,   g_wh);
    cudaGetSymbolAddress((void**)&wl,   g_wl);

    float* out = (float*)d_out;

    const int SM_BIG   = (2*128+2*128)*LDS_B*2;   // 81920 (2 stages)
    const int SM_SMALL = (2*64+2*64)*LDS_B*3;     // 61440 (3 stages)
    cudaFuncSetAttribute(mma_gemm<0,128,128,256,2>, cudaFuncAttributeMaxDynamicSharedMemorySize, SM_BIG);
    cudaFuncSetAttribute(mma_gemm<1,128,128,256,2>, cudaFuncAttributeMaxDynamicSharedMemorySize, SM_BIG);
    cudaFuncSetAttribute(mma_gemm<0,64,64,256,3>,   cudaFuncAttributeMaxDynamicSharedMemorySize, SM_SMALL);
    cudaFuncSetAttribute(mma_gemm<2,64,64,256,3>,   cudaFuncAttributeMaxDynamicSharedMemorySize, SM_SMALL);
    cudaFuncSetAttribute(attn_kernel, cudaFuncAttributeMaxDynamicSharedMemorySize, ATTN_SMEM);

    split_all<<<(W_TOT/4 + 255)/256, 256>>>(qkvw, outw, ff1w, ff2w, uw, hw, wh, wl);

    embed_kernel<<<TOK, 256>>>(marg, convw, convb, fcw, fcb, ln0g, ln0b, pos, xs, xsh, xsl);

    const unsigned GY128 = (TOK + 127) / 128;   // 9
    const unsigned GY64  = (TOK + 63) / 64;     // 17
    for (int l = 0; l < LL; l++) {
        mma_gemm<0,128,128,256,2><<<dim3(3*DD/128, GY128), 256, SM_BIG>>>(
            xsh, xsl, wh + W_QKV + (size_t)l*3*DD*DD, wl + W_QKV + (size_t)l*3*DD*DD,
            qkvb + l*3*DD, nullptr, qkv, nullptr, nullptr, nullptr, TOK, 3*DD, DD);
        attn_kernel<<<BB*HH, 512, ATTN_SMEM>>>(qkv, ath, atl);
        mma_gemm<0,64,64,256,3><<<dim3(DD/64, GY64), 256, SM_SMALL>>>(
            ath, atl, wh + W_OUT + (size_t)l*DD*DD, wl + W_OUT + (size_t)l*DD*DD,
            outb + l*DD, nullptr, tmp, nullptr, nullptr, nullptr, TOK, DD, DD);
        ln_res_kernel<<<TOK, 256>>>(tmp, ln1g + l*DD, ln1b + l*DD, xs, xsh, xsl);
        mma_gemm<1,128,128,256,2><<<dim3(DFF/128, GY128), 256, SM_BIG>>>(
            xsh, xsl, wh + W_FF1 + (size_t)l*DFF*DD, wl + W_FF1 + (size_t)l*DFF*DD,
            ff1b + l*DFF, nullptr, nullptr, nullptr, ffh, ffl, TOK, DFF, DD);
        mma_gemm<0,64,64,256,3><<<dim3(DD/64, GY64), 256, SM_SMALL>>>(
            ffh, ffl, wh + W_FF2 + (size_t)l*DD*DFF, wl + W_FF2 + (size_t)l*DD*DFF,
            ff2b + l*DD, nullptr, tmp, nullptr, nullptr, nullptr, TOK, DD, DFF);
        ln_res_kernel<<<TOK, 256>>>(tmp, ln2g + l*DD, ln2b + l*DD, xs, xsh, xsl);
    }

    // merged u/h GEMM: W rows 0..255 = u_w, 256..511 = h_w (contiguous in arena)
    mma_gemm<2,64,64,256,3><<<dim3(512/64, GY64), 256, SM_SMALL>>>(
        xsh, xsl, wh + W_U, wl + W_U, ub, hb, out, hraw, nullptr, nullptr, TOK, 512, DD);

    tail_kernel<<<BB*64, 256>>>(hraw, marg, xg, out + (size_t)TOK*MM);
}

// round 12
// speedup vs baseline: 1.4592x; 1.4592x over previous
#include <cuda_runtime.h>
#include <cuda_bf16.h>
#include <math.h>
#include <stdint.h>

// Problem constants
#define BB    16
#define NP1   65
#define TOK   (BB*NP1)      // 1040
#define MM    256
#define DD    512
#define HH    8
#define DH    64
#define LL    3
#define DFF   2048

// ---------------- weight arena offsets (elements) ---------------------------
#define W_QKV 0
#define W_OUT 2359296
#define W_FF1 3145728
#define W_FF2 6291456
#define W_U   9437184
#define W_H   9568256
#define W_TOT 9699328

// ---------------- scratch (device globals; no allocation allowed) ----------
__device__ __align__(128) float          g_xs  [TOK*DD];
__device__ __align__(128) __nv_bfloat16  g_xsh [TOK*DD];
__device__ __align__(128) __nv_bfloat16  g_xsl [TOK*DD];
__device__ __align__(128) float          g_qkv [TOK*3*DD];
__device__ __align__(128) __nv_bfloat16  g_ath [TOK*DD];
__device__ __align__(128) __nv_bfloat16  g_atl [TOK*DD];
__device__ __align__(128) float          g_tmp [TOK*DD];
__device__ __align__(128) __nv_bfloat16  g_ffh [TOK*DFF];
__device__ __align__(128) __nv_bfloat16  g_ffl [TOK*DFF];
__device__ __align__(128) float          g_hraw[TOK*MM];
__device__ __align__(128) __nv_bfloat16  g_wh  [W_TOT];
__device__ __align__(128) __nv_bfloat16  g_wl  [W_TOT];

// ---------------- PTX helpers (portable to bare sm_103) ---------------------
__device__ __forceinline__ uint32_t s2u(const void* p) {
    uint32_t a;
    asm("{ .reg .u64 t; cvta.to.shared.u64 t, %1; cvt.u32.u64 %0, t; }" : "=r"(a) : "l"(p));
    return a;
}
__device__ __forceinline__ void cp16(uint32_t dst, const void* src) {
    unsigned long long g = (unsigned long long)__cvta_generic_to_global(src);
    asm volatile("cp.async.cg.shared.global [%0], [%1], 16;" :: "r"(dst), "l"(g) : "memory");
}
#define CP_COMMIT() asm volatile("cp.async.commit_group;" ::: "memory")
#define CP_WAIT(n)  asm volatile("cp.async.wait_group %0;" :: "n"(n) : "memory")

__device__ __forceinline__ void ldm4(uint32_t* r, uint32_t a) {
    asm volatile("ldmatrix.sync.aligned.m8n8.x4.shared.b16 {%0,%1,%2,%3}, [%4];"
        : "=r"(r[0]), "=r"(r[1]), "=r"(r[2]), "=r"(r[3]) : "r"(a));
}
__device__ __forceinline__ void mma16816(float* c, const uint32_t* a, uint32_t b0, uint32_t b1) {
    asm volatile("mma.sync.aligned.m16n8k16.row.col.f32.bf16.bf16.f32 "
        "{%0,%1,%2,%3}, {%4,%5,%6,%7}, {%8,%9}, {%0,%1,%2,%3};"
        : "+f"(c[0]), "+f"(c[1]), "+f"(c[2]), "+f"(c[3])
        : "r"(a[0]), "r"(a[1]), "r"(a[2]), "r"(a[3]), "r"(b0), "r"(b1));
}

// ---------------- fused weight split: fp32 arena -> bf16 hi/lo --------------
__global__ __launch_bounds__(256)
void split_all(const float* __restrict__ qkvw, const float* __restrict__ outw,
               const float* __restrict__ ff1w, const float* __restrict__ ff2w,
               const float* __restrict__ uw,   const float* __restrict__ hw,
               __nv_bfloat16* __restrict__ wh, __nv_bfloat16* __restrict__ wl)
{
    size_t i = ((size_t)blockIdx.x*256 + threadIdx.x)*4;
    if (i >= W_TOT) return;
    const float* src;
    if      (i < W_OUT) src = qkvw + i;
    else if (i < W_FF1) src = outw + (i - W_OUT);
    else if (i < W_FF2) src = ff1w + (i - W_FF1);
    else if (i < W_U)   src = ff2w + (i - W_FF2);
    else if (i < W_H)   src = uw   + (i - W_U);
    else                src = hw   + (i - W_H);
    float4 v = *(const float4*)src;
    __nv_bfloat16 h0 = __float2bfloat16_rn(v.x), h1 = __float2bfloat16_rn(v.y);
    __nv_bfloat16 h2 = __float2bfloat16_rn(v.z), h3 = __float2bfloat16_rn(v.w);
    __nv_bfloat162 hp0; hp0.x = h0; hp0.y = h1;
    __nv_bfloat162 hp1; hp1.x = h2; hp1.y = h3;
    ((__nv_bfloat162*)(wh + i))[0] = hp0;
    ((__nv_bfloat162*)(wh + i))[1] = hp1;
    __nv_bfloat162 lp0, lp1;
    lp0.x = __float2bfloat16_rn(v.x - __bfloat162float(h0));
    lp0.y = __float2bfloat16_rn(v.y - __bfloat162float(h1));
    lp1.x = __float2bfloat16_rn(v.z - __bfloat162float(h2));
    lp1.y = __float2bfloat16_rn(v.w - __bfloat162float(h3));
    ((__nv_bfloat162*)(wl + i))[0] = lp0;
    ((__nv_bfloat162*)(wl + i))[1] = lp1;
}

// ---------------- HMMA GEMM: C[m,n] = sum_k A[m,k]*W[n,k] + bias ------------
// Tile BM x BN, NTHR threads. Warps: WM(M) x BN/32(N); warp tile (BM/WM)x32.
// NST-stage cp.async pipeline, K-chunk 32. 3-term split: Ah*Wh + Ah*Wl + Al*Wh.
#define LDS_B 80     // padded row stride (64B payload + 16B pad)

template<int BM, int BN, int NTHR>
__device__ __forceinline__ void load_chunk(uint32_t sb, int stage,
    const __nv_bfloat16* Ah, const __nv_bfloat16* Al,
    const __nv_bfloat16* Wh, const __nv_bfloat16* Wl,
    int m0, int n0, int k0, int M, int K, int tid)
{
    constexpr int AS_LO = BM*LDS_B;
    constexpr int WS_HI = 2*BM*LDS_B;
    constexpr int WS_LO = (2*BM+BN)*LDS_B;
    constexpr int STG   = (2*BM+2*BN)*LDS_B;
    constexpr int AIT   = (BM*4)/NTHR;
    constexpr int WIT   = (BN*4)/NTHR;
    uint32_t st = sb + stage*STG;
    #pragma unroll
    for (int p = 0; p < AIT; p++) {
        int idx = tid + p*NTHR;
        int row = idx >> 2, g = idx & 3;
        int ar = m0 + row; if (ar >= M) ar = M - 1;
        size_t off = (size_t)ar*K + k0 + g*8;
        uint32_t d = row*LDS_B + g*16;
        cp16(st + d,         Ah + off);
        cp16(st + AS_LO + d, Al + off);
    }
    #pragma unroll
    for (int p = 0; p < WIT; p++) {
        int idx = tid + p*NTHR;
        int row = idx >> 2, g = idx & 3;
        size_t off = (size_t)(n0 + row)*K + k0 + g*8;
        uint32_t d = row*LDS_B + g*16;
        cp16(st + WS_HI + d, Wh + off);
        cp16(st + WS_LO + d, Wl + off);
    }
}

template<int EPI, int BM, int BN, int NTHR, int NST>
__global__ __launch_bounds__(NTHR, 2)
void mma_gemm(const __nv_bfloat16* __restrict__ Ah, const __nv_bfloat16* __restrict__ Al,
              const __nv_bfloat16* __restrict__ Wh, const __nv_bfloat16* __restrict__ Wl,
              const float* __restrict__ b0, const float* __restrict__ b1,
              float* __restrict__ C0, float* __restrict__ C1,
              __nv_bfloat16* __restrict__ Ch, __nv_bfloat16* __restrict__ Cl,
              int M, int N, int K)
{
    extern __shared__ char smem[];
    constexpr int NWARP = NTHR/32;
    constexpr int WN    = BN/32;
    constexpr int WMCNT = NWARP/WN;
    constexpr int WROWS = BM/WMCNT;
    constexpr int IT    = WROWS/16;
    constexpr int AS_LO = BM*LDS_B;
    constexpr int WS_HI = 2*BM*LDS_B;
    constexpr int STG   = (2*BM+2*BN)*LDS_B;
    uint32_t sb = s2u(smem);
    int tid = threadIdx.x, wid = tid >> 5, lane = tid & 31;
    int wm = wid / WN, wn = wid % WN;
    int m0 = blockIdx.y * BM, n0 = blockIdx.x * BN;
    const int NC = K >> 5;

    float c[IT][4][4];
    #pragma unroll
    for (int i = 0; i < IT; i++)
        #pragma unroll
        for (int j = 0; j < 4; j++)
            #pragma unroll
            for (int q = 0; q < 4; q++) c[i][j][q] = 0.f;

    #pragma unroll
    for (int s = 0; s < NST; s++) {
        load_chunk<BM,BN,NTHR>(sb, s, Ah, Al, Wh, Wl, m0, n0, s*32, M, K, tid);
        CP_COMMIT();
    }

    uint32_t lrow = (lane & 15);
    uint32_t koff = (lane >> 4) * 16;

    for (int cc = 0; cc < NC; cc++) {
        CP_WAIT(NST - 1);
        __syncthreads();
        uint32_t st = sb + (cc % NST)*STG;
        #pragma unroll
        for (int ks = 0; ks < 2; ks++) {
            uint32_t kb = ks*32 + koff;
            uint32_t bh[2][4], bl[2][4];
            #pragma unroll
            for (int j2 = 0; j2 < 2; j2++) {
                uint32_t rb = st + WS_HI + (wn*32 + j2*16 + lrow)*LDS_B + kb;
                ldm4(bh[j2], rb);
                ldm4(bl[j2], rb + BN*LDS_B);
            }
            #pragma unroll
            for (int i = 0; i < IT; i++) {
                uint32_t ra = st + (wm*WROWS + i*16 + lrow)*LDS_B + kb;
                uint32_t ah[4], al[4];
                ldm4(ah, ra);
                ldm4(al, ra + AS_LO);
                #pragma unroll
                for (int j2 = 0; j2 < 2; j2++) {
                    #pragma unroll
                    for (int jj = 0; jj < 2; jj++) {
                        float* acc = c[i][2*j2 + jj];
                        mma16816(acc, ah, bh[j2][jj], bh[j2][jj+2]);
                        mma16816(acc, ah, bl[j2][jj], bl[j2][jj+2]);
                        mma16816(acc, al, bh[j2][jj], bh[j2][jj+2]);
                    }
                }
            }
        }
        __syncthreads();
        if (cc + NST < NC)
            load_chunk<BM,BN,NTHR>(sb, cc % NST, Ah, Al, Wh, Wl, m0, n0, (cc+NST)*32, M, K, tid);
        CP_COMMIT();
    }

    // epilogue
    int rbase = m0 + wm*WROWS + (lane >> 2);
    int cbase = n0 + wn*32 + 2*(lane & 3);
    #pragma unroll
    for (int i = 0; i < IT; i++) {
        #pragma unroll
        for (int j = 0; j < 4; j++) {
            int col = cbase + j*8;
            float bb0 = b0[col], bb1 = b0[col+1];
            #pragma unroll
            for (int half = 0; half < 2; half++) {
                int r = rbase + i*16 + half*8;
                if (r >= M) continue;
                float v0 = c[i][j][2*half + 0] + bb0;
                float v1 = c[i][j][2*half + 1] + bb1;
                if (EPI == 0) {
                    *(float2*)(C0 + (size_t)r*N + col) = make_float2(v0, v1);
                } else if (EPI == 1) {
                    v0 = 0.5f*v0*(1.0f + erff(v0*0.70710678118654752f));
                    v1 = 0.5f*v1*(1.0f + erff(v1*0.70710678118654752f));
                    __nv_bfloat16 h0 = __float2bfloat16_rn(v0);
                    __nv_bfloat16 h1 = __float2bfloat16_rn(v1);
                    __nv_bfloat162 hp; hp.x = h0; hp.y = h1;
                    __nv_bfloat162 lp;
                    lp.x = __float2bfloat16_rn(v0 - __bfloat162float(h0));
                    lp.y = __float2bfloat16_rn(v1 - __bfloat162float(h1));
                    *(__nv_bfloat162*)(Ch + (size_t)r*N + col) = hp;
                    *(__nv_bfloat162*)(Cl + (size_t)r*N + col) = lp;
                } else {
                    if (col < 256) {
                        *(float2*)(C0 + (size_t)r*256 + col) = make_float2(v0, v1);
                    } else {
                        float u0 = c[i][j][2*half+0] + b1[col-256];
                        float u1 = c[i][j][2*half+1] + b1[col-255];
                        *(float2*)(C1 + (size_t)r*256 + (col-256)) = make_float2(u0, u1);
                    }
                }
            }
        }
    }
}

// ---------------- embed: conv-collapse + fc + LN + GELU + pos --------------
__global__ __launch_bounds__(256)
void embed_kernel(const float* __restrict__ marg, const float* __restrict__ conv_w,
                  const float* __restrict__ conv_b, const float* __restrict__ fc_w,
                  const float* __restrict__ fc_b, const float* __restrict__ ln_g,
                  const float* __restrict__ ln_b, const float* __restrict__ pos,
                  float* __restrict__ xs, __nv_bfloat16* __restrict__ xsh,
                  __nv_bfloat16* __restrict__ xsl)
{
    int row = blockIdx.x;
    int tid = threadIdx.x;
    __shared__ float red[256];
    __shared__ float e[128];

    const float* x = marg + (size_t)row * MM;
    red[tid] = x[tid];
    __syncthreads();
    for (int s = 128; s > 0; s >>= 1) { if (tid < s) red[tid] += red[tid+s]; __syncthreads(); }
    float S = red[0];
    __syncthreads();

    if (tid < 128) {
        float x0 = x[0], x1 = x[1], xm2 = x[MM-2], xm1 = x[MM-1];
        const float* w = conv_w + tid*5;
        float acc = w[0]*(S - xm2 - xm1) + w[1]*(S - xm1) + w[2]*S
                  + w[3]*(S - x0)        + w[4]*(S - x0 - x1);
        e[tid] = conv_b[tid] + acc * (1.0f/(float)MM);
    }
    __syncthreads();

    float t0 = fc_b[tid], t1 = fc_b[tid+256];
    #pragma unroll 4
    for (int c = 0; c < 128; c++) {
        float ec = e[c];
        t0 += ec * fc_w[c*DD + tid];
        t1 += ec * fc_w[c*DD + tid + 256];
    }

    red[tid] = t0 + t1; __syncthreads();
    for (int s = 128; s > 0; s >>= 1) { if (tid < s) red[tid] += red[tid+s]; __syncthreads(); }
    float mean = red[0] * (1.0f/(float)DD);
    __syncthreads();
    float d0 = t0 - mean, d1 = t1 - mean;
    red[tid] = d0*d0 + d1*d1; __syncthreads();
    for (int s = 128; s > 0; s >>= 1) { if (tid < s) red[tid] += red[tid+s]; __syncthreads(); }
    float inv = rsqrtf(red[0] * (1.0f/(float)DD) + 1e-5f);

    float y0 = d0*inv*ln_g[tid]     + ln_b[tid];
    float y1 = d1*inv*ln_g[tid+256] + ln_b[tid+256];
    y0 = 0.5f*y0*(1.0f + erff(y0*0.70710678118654752f));
    y1 = 0.5f*y1*(1.0f + erff(y1*0.70710678118654752f));

    int p = row % NP1;
    float v0 = y0 + pos[p*DD + tid];
    float v1 = y1 + pos[p*DD + tid + 256];
    size_t base = (size_t)row*DD;
    xs[base + tid] = v0; xs[base + tid + 256] = v1;
    __nv_bfloat16 h0 = __float2bfloat16_rn(v0), h1 = __float2bfloat16_rn(v1);
    xsh[base + tid] = h0;        xsh[base + tid + 256] = h1;
    xsl[base + tid] = __float2bfloat16_rn(v0 - __bfloat162float(h0));
    xsl[base + tid + 256] = __float2bfloat16_rn(v1 - __bfloat162float(h1));
}

// ---------------- attention: one block per (b,h), 16 warps, 4 queries/warp -
// Single pass: warp w handles queries 4w..4w+3 as 4 ILP streams sharing K/V
// smem loads. Query 64 handled by warp 0 in a short single-stream tail.
#define ATTN_SMEM ((NP1*65 + NP1*64 + 64*68)*4)   // Ks + Vs + Ps

__global__ __launch_bounds__(512)
void attn_kernel(const float* __restrict__ qkv, __nv_bfloat16* __restrict__ ah,
                 __nv_bfloat16* __restrict__ al)
{
    extern __shared__ float asm_f[];
    float (*Ks)[65] = (float(*)[65])asm_f;                       // [NP1][65]
    float (*Vs)[64] = (float(*)[64])(asm_f + NP1*65);            // [NP1][64]
    float (*Ps)[68] = (float(*)[68])(asm_f + NP1*65 + NP1*64);   // [64][68]

    int bh = blockIdx.x;
    int b = bh >> 3, h = bh & 7;
    int tid = threadIdx.x, lane = tid & 31, w = tid >> 5;   // w: 0..15

    for (int idx = tid; idx < NP1*64; idx += 512) {
        int j = idx >> 6, k = idx & 63;
        size_t base = ((size_t)(b*NP1 + j))*(3*DD) + h*DH + k;
        Ks[j][k] = qkv[base + DD];
        Vs[j][k] = qkv[base + 2*DD];
    }
    __syncthreads();

    const float scale = 0.125f;
    const unsigned FULL = 0xffffffffu;
    int q0 = w*4;

    float2 qp[4];
    #pragma unroll
    for (int s = 0; s < 4; s++)
        qp[s] = *(const float2*)(qkv + ((size_t)(b*NP1 + q0 + s))*(3*DD) + h*DH + 2*lane);

    float sc[4][3];
    #pragma unroll
    for (int s = 0; s < 4; s++) { sc[s][0] = 0.f; sc[s][1] = 0.f; sc[s][2] = 0.f; }

    #pragma unroll
    for (int k = 0; k < 64; k++) {
        float k0 = Ks[lane][k], k1 = Ks[lane + 32][k], k2 = Ks[64][k];
        #pragma unroll
        for (int s = 0; s < 4; s++) {
            float qv = __shfl_sync(FULL, (k & 1) ? qp[s].y : qp[s].x, k >> 1);
            sc[s][0] = fmaf(qv, k0, sc[s][0]);
            sc[s][1] = fmaf(qv, k1, sc[s][1]);
            sc[s][2] = fmaf(qv, k2, sc[s][2]);
        }
    }

    float mx[4], e0[4], e1[4], e2[4], ls[4], rinv[4];
    #pragma unroll
    for (int s = 0; s < 4; s++) {
        sc[s][0] *= scale; sc[s][1] *= scale; sc[s][2] *= scale;
        mx[s] = fmaxf(fmaxf(sc[s][0], sc[s][1]), sc[s][2]);
    }
    #pragma unroll
    for (int o = 16; o > 0; o >>= 1)
        #pragma unroll
        for (int s = 0; s < 4; s++)
            mx[s] = fmaxf(mx[s], __shfl_xor_sync(FULL, mx[s], o));
    #pragma unroll
    for (int s = 0; s < 4; s++) {
        e0[s] = expf(sc[s][0] - mx[s]);
        e1[s] = expf(sc[s][1] - mx[s]);
        e2[s] = expf(sc[s][2] - mx[s]);
        ls[s] = e0[s] + e1[s];
    }
    #pragma unroll
    for (int o = 16; o > 0; o >>= 1)
        #pragma unroll
        for (int s = 0; s < 4; s++)
            ls[s] += __shfl_xor_sync(FULL, ls[s], o);
    #pragma unroll
    for (int s = 0; s < 4; s++) {
        rinv[s] = 1.0f / (ls[s] + e2[s]);
        Ps[q0 + s][lane]      = e0[s] * rinv[s];
        Ps[q0 + s][lane + 32] = e1[s] * rinv[s];
        if (lane == 0) Ps[q0 + s][64] = e2[s] * rinv[s];
    }
    __syncwarp();

    float o0[4], o1[4];
    #pragma unroll
    for (int s = 0; s < 4; s++) { o0[s] = 0.f; o1[s] = 0.f; }
    #pragma unroll 5
    for (int j = 0; j < NP1; j++) {
        float v0 = Vs[j][lane], v1 = Vs[j][lane + 32];
        #pragma unroll
        for (int s = 0; s < 4; s++) {
            float pj = Ps[q0 + s][j];
            o0[s] = fmaf(pj, v0, o0[s]);
            o1[s] = fmaf(pj, v1, o1[s]);
        }
    }
    #pragma unroll
    for (int s = 0; s < 4; s++) {
        size_t obase = ((size_t)(b*NP1 + q0 + s))*DD + h*DH;
        __nv_bfloat16 h0 = __float2bfloat16_rn(o0[s]), h1 = __float2bfloat16_rn(o1[s]);
        ah[obase + lane]      = h0;
        ah[obase + lane + 32] = h1;
        al[obase + lane]      = __float2bfloat16_rn(o0[s] - __bfloat162float(h0));
        al[obase + lane + 32] = __float2bfloat16_rn(o1[s] - __bfloat162float(h1));
    }

    // tail: query 64 on warp 0 only (other warps done)
    if (w == 0) {
        __syncwarp();
        float2 qt = *(const float2*)(qkv + ((size_t)(b*NP1 + 64))*(3*DD) + h*DH + 2*lane);
        float t0 = 0.f, t1 = 0.f, t2 = 0.f;
        #pragma unroll
        for (int k = 0; k < 64; k++) {
            float qv = __shfl_sync(FULL, (k & 1) ? qt.y : qt.x, k >> 1);
            t0 = fmaf(qv, Ks[lane][k],      t0);
            t1 = fmaf(qv, Ks[lane + 32][k], t1);
            t2 = fmaf(qv, Ks[64][k],        t2);
        }
        t0 *= scale; t1 *= scale; t2 *= scale;
        float m = fmaxf(fmaxf(t0, t1), t2);
        #pragma unroll
        for (int o = 16; o > 0; o >>= 1) m = fmaxf(m, __shfl_xor_sync(FULL, m, o));
        float f0 = expf(t0 - m), f1 = expf(t1 - m), f2 = expf(t2 - m);
        float l = f0 + f1;
        #pragma unroll
        for (int o = 16; o > 0; o >>= 1) l += __shfl_xor_sync(FULL, l, o);
        float ri = 1.0f / (l + f2);
        Ps[0][lane]      = f0 * ri;
        Ps[0][lane + 32] = f1 * ri;
        if (lane == 0) Ps[0][64] = f2 * ri;
        __syncwarp();
        float u0 = 0.f, u1 = 0.f;
        #pragma unroll 5
        for (int j = 0; j < NP1; j++) {
            float pj = Ps[0][j];
            u0 = fmaf(pj, Vs[j][lane],      u0);
            u1 = fmaf(pj, Vs[j][lane + 32], u1);
        }
        size_t obase = ((size_t)(b*NP1 + 64))*DD + h*DH;
        __nv_bfloat16 h0 = __float2bfloat16_rn(u0), h1 = __float2bfloat16_rn(u1);
        ah[obase + lane]      = h0;
        ah[obase + lane + 32] = h1;
        al[obase + lane]      = __float2bfloat16_rn(u0 - __bfloat162float(h0));
        al[obase + lane + 32] = __float2bfloat16_rn(u1 - __bfloat162float(h1));
    }
}

// ---------------- residual + LayerNorm (in place on xs), emits hi/lo -------
__global__ __launch_bounds__(256)
void ln_res_kernel(const float* __restrict__ add, const float* __restrict__ g,
                   const float* __restrict__ bta, float* __restrict__ xs,
                   __nv_bfloat16* __restrict__ xsh, __nv_bfloat16* __restrict__ xsl)
{
    int row = blockIdx.x, tid = threadIdx.x;
    __shared__ float red[256];
    size_t base = (size_t)row*DD;
    float v0 = xs[base + tid]       + add[base + tid];
    float v1 = xs[base + tid + 256] + add[base + tid + 256];

    red[tid] = v0 + v1; __syncthreads();
    for (int s = 128; s > 0; s >>= 1) { if (tid < s) red[tid] += red[tid+s]; __syncthreads(); }
    float mean = red[0] * (1.0f/(float)DD);
    __syncthreads();
    float d0 = v0 - mean, d1 = v1 - mean;
    red[tid] = d0*d0 + d1*d1; __syncthreads();
    for (int s = 128; s > 0; s >>= 1) { if (tid < s) red[tid] += red[tid+s]; __syncthreads(); }
    float inv = rsqrtf(red[0] * (1.0f/(float)DD) + 1e-5f);

    float y0 = d0*inv*g[tid]       + bta[tid];
    float y1 = d1*inv*g[tid + 256] + bta[tid + 256];
    xs[base + tid] = y0; xs[base + tid + 256] = y1;
    __nv_bfloat16 h0 = __float2bfloat16_rn(y0), h1 = __float2bfloat16_rn(y1);
    xsh[base + tid] = h0;        xsh[base + tid + 256] = h1;
    xsl[base + tid] = __float2bfloat16_rn(y0 - __bfloat162float(h0));
    xsl[base + tid + 256] = __float2bfloat16_rn(y1 - __bfloat162float(h1));
}

// ---------------- MMOT tail: closed-form truncated-geometric softmax -------
__global__ __launch_bounds__(256)
void tail_kernel(const float* __restrict__ hraw, const float* __restrict__ marg,
                 const float* __restrict__ xg, float* __restrict__ hout)
{
    int blk = blockIdx.x;
    int b = blk >> 6, n = blk & 63;
    int tid = threadIdx.x;
    int tok = b*NP1 + n;

    float hr = hraw[(size_t)tok*MM + tid];
    const float DELTA = 6.0f/255.0f;
    float t = hr * (DELTA / 0.01f);
    float q = expf(-fabsf(t));

    float S0 = 1.f, S1 = 0.f, p = q, mcnt = 1.f;
    #pragma unroll
    for (int it = 0; it < 8; it++) {
        S1 = S1 + p*(S1 + mcnt*S0);
        S0 = S0 + p*S0;
        p  = p*p;
        mcnt *= 2.f;
    }
    float f = S1 / S0;
    if (t < 0.f) f = 255.f - f;

    float expected = -3.f + DELTA * f;
    float drift = expected - xg[tid];
    float mu = marg[(size_t)tok*MM + tid];

    __shared__ float r1[256], r2[256];
    r1[tid] = mu * drift; r2[tid] = mu;
    __syncthreads();
    for (int s = 128; s > 0; s >>= 1) {
        if (tid < s) { r1[tid] += r1[tid+s]; r2[tid] += r2[tid+s]; }
        __syncthreads();
    }
    float corr = r1[0] / (r2[0] + 1e-8f);
    hout[(size_t)(b*64 + n)*MM + tid] = hr - corr;
}

// ---------------------------------------------------------------------------
extern "C" void kernel_launch(void* const* d_in, const int* in_sizes, int n_in,
                              void* d_out, int out_size)
{
    const float* marg  = (const float*)d_in[0];
    const float* xg    = (const float*)d_in[1];
    const float* convw = (const float*)d_in[2];
    const float* convb = (const float*)d_in[3];
    const float* fcw   = (const float*)d_in[4];
    const float* fcb   = (const float*)d_in[5];
    const float* ln0g  = (const float*)d_in[6];
    const float* ln0b  = (const float*)d_in[7];
    const float* pos   = (const float*)d_in[8];
    const float* qkvw  = (const float*)d_in[9];
    const float* qkvb  = (const float*)d_in[10];
    const float* outw  = (const float*)d_in[11];
    const float* outb  = (const float*)d_in[12];
    const float* ln1g  = (const float*)d_in[13];
    const float* ln1b  = (const float*)d_in[14];
    const float* ff1w  = (const float*)d_in[15];
    const float* ff1b  = (const float*)d_in[16];
    const float* ff2w  = (const float*)d_in[17];
    const float* ff2b  = (const float*)d_in[18];
    const float* ln2g  = (const float*)d_in[19];
    const float* ln2b  = (const float*)d_in[20];
    const float* uw    = (const float*)d_in[21];
    const float* ub    = (const float*)d_in[22];
    const float* hw    = (const float*)d_in[23];
    const float* hb    = (const float*)d_in[24];

    float *xs, *qkv, *tmp, *hraw;
    __nv_bfloat16 *xsh, *xsl, *ath, *atl, *ffh, *ffl, *wh, *wl;
    cudaGetSymbolAddress((void**)&xs,   g_xs);
    cudaGetSymbolAddress((void**)&xsh,  g_xsh);
    cudaGetSymbolAddress((void**)&xsl,  g_xsl);
    cudaGetSymbolAddress((void**)&qkv,  g_qkv);
    cudaGetSymbolAddress((void**)&ath,  g_ath);
    cudaGetSymbolAddress((void**)&atl,  g_atl);
    cudaGetSymbolAddress((void**)&tmp,  g_tmp);
    cudaGetSymbolAddress((void**)&ffh,  g_ffh);
    cudaGetSymbolAddress((void**)&ffl,  g_ffl);
    cudaGetSymbolAddress((void**)&hraw, g_hraw);
    cudaGetSymbolAddress((void**)&wh,   g_wh);
    cudaGetSymbolAddress((void**)&wl,   g_wl);

    float* out = (float*)d_out;

    const int SM_BIG   = (2*128+2*128)*LDS_B*2;   // 81920 (2 stages)
    const int SM_SMALL = (2*64+2*64)*LDS_B*3;     // 61440 (3 stages)
    cudaFuncSetAttribute(mma_gemm<0,128,128,256,2>, cudaFuncAttributeMaxDynamicSharedMemorySize, SM_BIG);
    cudaFuncSetAttribute(mma_gemm<1,128,128,256,2>, cudaFuncAttributeMaxDynamicSharedMemorySize, SM_BIG);
    cudaFuncSetAttribute(mma_gemm<0,64,64,256,3>,   cudaFuncAttributeMaxDynamicSharedMemorySize, SM_SMALL);
    cudaFuncSetAttribute(mma_gemm<2,64,64,256,3>,   cudaFuncAttributeMaxDynamicSharedMemorySize, SM_SMALL);
    cudaFuncSetAttribute(attn_kernel, cudaFuncAttributeMaxDynamicSharedMemorySize, ATTN_SMEM);

    split_all<<<(W_TOT/4 + 255)/256, 256>>>(qkvw, outw, ff1w, ff2w, uw, hw, wh, wl);

    embed_kernel<<<TOK, 256>>>(marg, convw, convb, fcw, fcb, ln0g, ln0b, pos, xs, xsh, xsl);

    const unsigned GY128 = (TOK + 127) / 128;   // 9
    const unsigned GY64  = (TOK + 63) / 64;     // 17
    for (int l = 0; l < LL; l++) {
        mma_gemm<0,128,128,256,2><<<dim3(3*DD/128, GY128), 256, SM_BIG>>>(
            xsh, xsl, wh + W_QKV + (size_t)l*3*DD*DD, wl + W_QKV + (size_t)l*3*DD*DD,
            qkvb + l*3*DD, nullptr, qkv, nullptr, nullptr, nullptr, TOK, 3*DD, DD);
        attn_kernel<<<BB*HH, 512, ATTN_SMEM>>>(qkv, ath, atl);
        mma_gemm<0,64,64,256,3><<<dim3(DD/64, GY64), 256, SM_SMALL>>>(
            ath, atl, wh + W_OUT + (size_t)l*DD*DD, wl + W_OUT + (size_t)l*DD*DD,
            outb + l*DD, nullptr, tmp, nullptr, nullptr, nullptr, TOK, DD, DD);
        ln_res_kernel<<<TOK, 256>>>(tmp, ln1g + l*DD, ln1b + l*DD, xs, xsh, xsl);
        mma_gemm<1,128,128,256,2><<<dim3(DFF/128, GY128), 256, SM_BIG>>>(
            xsh, xsl, wh + W_FF1 + (size_t)l*DFF*DD, wl + W_FF1 + (size_t)l*DFF*DD,
            ff1b + l*DFF, nullptr, nullptr, nullptr, ffh, ffl, TOK, DFF, DD);
        mma_gemm<0,64,64,256,3><<<dim3(DD/64, GY64), 256, SM_SMALL>>>(
            ffh, ffl, wh + W_FF2 + (size_t)l*DD*DFF, wl + W_FF2 + (size_t)l*DD*DFF,
            ff2b + l*DD, nullptr, tmp, nullptr, nullptr, nullptr, TOK, DD, DFF);
        ln_res_kernel<<<TOK, 256>>>(tmp, ln2g + l*DD, ln2b + l*DD, xs, xsh, xsl);
    }

    // merged u/h GEMM: W rows 0..255 = u_w, 256..511 = h_w (contiguous in arena)
    mma_gemm<2,64,64,256,3><<<dim3(512/64, GY64), 256, SM_SMALL>>>(
        xsh, xsl, wh + W_U, wl + W_U, ub, hb, out, hraw, nullptr, nullptr, TOK, 512, DD);

    tail_kernel<<<BB*64, 256>>>(hraw, marg, xg, out + (size_t)TOK*MM);
}